// round 16
// baseline (speedup 1.0000x reference)
#include <cuda_runtime.h>

// Problem constants
#define CCH   96
#define TT    1000
#define FF    64
#define LL    12
#define PP    8           // parts = batch elements (zero conv halo)
#define NT    384         // 96 c-lanes x 4 col-groups (16 cols/thread)
#define DD    8           // state ring depth
#define WW    64
#define EPSF  1e-6f
#define TILE  (CCH * WW)  // 6144
#define NPAN  12          // weight panels per GEMM
#define PK    8           // k per panel
#define PANU  2304        // u64 per path-panel (3*8*96)

// ---------------- device globals (no runtime alloc) ------------------------
__device__ float  g_hbuf[LL * DD * PP * TILE];   // output ring (18.9 MB)
__device__ float  g_rs  [LL * DD * PP * WW];     // published rms stats
__device__ float2 g_xwd [LL * 3 * CCH * CCH];    // x-weights duplicated {w,w} [l][d][k][c]
__device__ float2 g_hwd [LL * 3 * CCH * CCH];    // h-weights duplicated {w,w}
__device__ float  g_pbF [LL * 288];              // pb + pw . hb
__device__ int    g_prog[LL * PP * 32];          // flags, 128B padded

// smem layout (floats)
#define OFF_Y    0         // raw y            6144
#define OFF_HP   6144      // prev output      6144
#define OFF_HC   12288     // conv / s-buffer  6144
#define OFF_RY   18432     // 64
#define OFF_RH   18496     // 64
#define OFF_RO   18560     // 64
#define OFF_SCR  18624     // reduction scratch 768
#define OFF_ONW  19392     // 96
#define OFF_XB   19488     // 288
#define OFF_PB   19776     // 288
#define OFF_HWT  20064     // conv taps [d][c] 3*96
#define OFF_WP   20352     // weight staging: 2 bufs x 2 paths x 2304 u64 = 18432 floats
#define SMEM_FLOATS 38784
#define SMEM_BYTES  (SMEM_FLOATS * 4)   // 155,136 B

typedef unsigned long long u64;

__device__ __forceinline__ u64 fma2(u64 a, u64 b, u64 c) {
    u64 d;
    asm("fma.rn.f32x2 %0, %1, %2, %3;" : "=l"(d) : "l"(a), "l"(b), "l"(c));
    return d;
}
__device__ __forceinline__ float2 unpack2(u64 v) {
    float2 r; asm("mov.b64 {%0, %1}, %2;" : "=f"(r.x), "=f"(r.y) : "l"(v)); return r;
}
__device__ __forceinline__ int ld_vol(const int* p) {
    int v;
    asm volatile("ld.volatile.global.b32 %0, [%1];" : "=r"(v) : "l"(p) : "memory");
    return v;
}
__device__ __forceinline__ void st_vol(int* p, int v) {
    asm volatile("st.volatile.global.b32 [%0], %1;" :: "l"(p), "r"(v) : "memory");
}
__device__ __forceinline__ void spin_ge(const int* p, int tgt) {
    while (ld_vol(p) < tgt) {
#if __CUDA_ARCH__ >= 700
        __nanosleep(40);
#endif
    }
}
__device__ __forceinline__ float fsigm(float x) {
    return __fdividef(1.f, 1.f + __expf(-x));
}
__device__ __forceinline__ float ftanh(float x) {
    float e = __expf(2.f * x);
    return 1.f - __fdividef(2.f, 1.f + e);
}
#define CP_COMMIT() asm volatile("cp.async.commit_group;")
#define CP_WAIT0()  asm volatile("cp.async.wait_group 0;")
__device__ __forceinline__ void cp16(unsigned dst, const float4* src) {
    asm volatile("cp.async.ca.shared.global [%0], [%1], 16;" :: "r"(dst), "l"(src));
}

// ---------------- init: flags + duplicated-weight folding ------------------
__global__ void gru_init(const float* __restrict__ xw, const float* __restrict__ pw,
                         const float* __restrict__ inw, const float* __restrict__ hnw,
                         const float* __restrict__ hb,  const float* __restrict__ pb) {
    int idx = blockIdx.x * blockDim.x + threadIdx.x;
    int stride = gridDim.x * blockDim.x;
    for (int i = idx; i < LL * PP * 32; i += stride) g_prog[i] = 0;
    const int NW = LL * CCH * CCH;
    for (int i = idx; i < NW; i += stride) {
        int l = i / (CCH * CCH), r = i - l * (CCH * CCH);
        int k = r / CCH, c = r - k * CCH;
        float fin = inw[l * CCH + k], fhn = hnw[l * CCH + k];
        #pragma unroll
        for (int d = 0; d < 3; ++d) {
            float wx = xw[(l * 288 + d * CCH + c) * CCH + k] * fin;
            float wh = pw[(l * 288 + d * CCH + c) * CCH + k] * fhn;
            g_xwd[(((size_t)l * 3 + d) * CCH + k) * CCH + c] = make_float2(wx, wx);
            g_hwd[(((size_t)l * 3 + d) * CCH + k) * CCH + c] = make_float2(wh, wh);
        }
    }
    for (int i = idx; i < LL * 288; i += stride) {
        int l = i / 288, o = i - l * 288;
        float s = pb[i];
        for (int k = 0; k < CCH; ++k) s += pw[(l * 288 + o) * CCH + k] * hb[l * CCH + k];
        g_pbF[i] = s;
    }
}

// ---------------- main persistent wavefront kernel -------------------------
__global__ void __launch_bounds__(NT, 1) gru_main(
    const float* __restrict__ x,
    const float* __restrict__ xpb_g,
    const float* __restrict__ hw_g,
    const float* __restrict__ onw_g,
    float* __restrict__ out)
{
    extern __shared__ float sm[];
    const int tid  = threadIdx.x;
    const int l    = blockIdx.x / PP;
    const int part = blockIdx.x % PP;      // = batch element

    // ---- one-time: params into smem ----
    for (int i = tid; i < CCH; i += NT) {
        sm[OFF_ONW + i]       = onw_g[l * CCH + i];
        sm[OFF_HWT       + i] = hw_g[(l * CCH + i) * 3 + 0];
        sm[OFF_HWT +  96 + i] = hw_g[(l * CCH + i) * 3 + 1];
        sm[OFF_HWT + 192 + i] = hw_g[(l * CCH + i) * 3 + 2];
    }
    for (int i = tid; i < 288; i += NT) {
        sm[OFF_XB + i] = xpb_g[l * 288 + i];
        sm[OFF_PB + i] = g_pbF[l * 288 + i];
    }
    for (int i = tid; i < TILE; i += NT) sm[OFF_HP + i] = 0.f;
    if (tid < WW) sm[OFF_RH + tid] = 0.f;
    __syncthreads();

    const int c  = tid % CCH;
    const int mb = (tid / CCH) * 16;       // 16 cols per thread
    const float xb0 = sm[OFF_XB + c], xb1 = sm[OFF_XB + 96 + c], xb2 = sm[OFF_XB + 192 + c];
    const float pb0 = sm[OFF_PB + c], pb1 = sm[OFF_PB + 96 + c], pb2 = sm[OFF_PB + 192 + c];

    // weight panel staging setup (both paths, duplicated u64 pairs)
    unsigned wpbase;
    {
        const float* p0 = sm + OFF_WP;
        asm("{ .reg .u64 t; cvta.to.shared.u64 t, %1; cvt.u32.u64 %0, t; }"
            : "=r"(wpbase) : "l"(p0));
    }
    const float4* __restrict__ gx = (const float4*)(g_xwd + (size_t)l * 3 * CCH * CCH);
    const float4* __restrict__ gh = (const float4*)(g_hwd + (size_t)l * 3 * CCH * CCH);
    // per-thread staging coords: 6 float4 per panel (2*2304 u64 = 2304 float4)
    int s_path[6], s_row[6], s_c4[6];
    #pragma unroll
    for (int i = 0; i < 6; ++i) {
        int f = tid + i * NT;              // 0..2303
        int pth = f / 1152;                // 0 = x, 1 = h
        int r   = f - pth * 1152;
        s_path[i] = pth;
        s_row[i]  = r / 48;                // (d*PK + kk), 0..23
        s_c4[i]   = r - (r / 48) * 48;     // 0..47
    }

    int* myflag = &g_prog[(l * PP + part) * 32];

    #pragma unroll 1
    for (int t = 0; t < TT; ++t) {
        const int slot = t & (DD - 1);

        // ---- pre-spin: x load (pure input) + own conv ----
        if (l == 0) {
            #pragma unroll
            for (int i = 0; i < 4; ++i) {
                int f4 = tid + i * NT;
                int cc = f4 >> 4, j = f4 & 15;
                ((float4*)(sm + OFF_Y))[f4] =
                    __ldg((const float4*)(x + (((size_t)part * CCH + cc) * TT + t) * FF) + j);
            }
        }
        #pragma unroll
        for (int i = 0; i < 16; ++i) {
            int idx = tid + i * NT;
            int cc = idx >> 6, m = idx & 63;
            float acc = sm[OFF_HP + idx] * sm[OFF_RH + m] * sm[OFF_HWT + 96 + cc];
            if (m != 0)  acc += sm[OFF_HP + idx - 1] * sm[OFF_RH + m - 1] * sm[OFF_HWT + cc];
            if (m != 63) acc += sm[OFF_HP + idx + 1] * sm[OFF_RH + m + 1] * sm[OFF_HWT + 192 + cc];
            sm[OFF_HC + idx] = acc;
        }

        // prestage weight panel 0 into buf0 (prev step drained both buffers)
        #pragma unroll
        for (int i = 0; i < 6; ++i) {
            const float4* src = (s_path[i] ? gh : gx) +
                ((s_row[i] / PK) * CCH + (s_row[i] & (PK - 1))) * 48 + s_c4[i];
            unsigned dst = wpbase +
                (unsigned)(s_path[i] * PANU + s_row[i] * CCH + s_c4[i] * 2) * 8u;
            cp16(dst, src);
        }
        CP_COMMIT();

        // ---- dependency spin (tid 0): up data-ready / down ring-free ----
        if (tid == 0) {
            if (l > 0)                 spin_ge(&g_prog[((l - 1) * PP + part) * 32], t + 1);
            if (l < LL - 1 && t >= DD) spin_ge(&g_prog[((l + 1) * PP + part) * 32], t - DD + 1);
        }
        __syncthreads();

        // ---- Phase A: y + RY from upstream (L1-bypass) ----
        if (l > 0) {
            const float4* ys = (const float4*)(g_hbuf +
                ((size_t)((l - 1) * DD + slot) * PP + part) * TILE);
            #pragma unroll
            for (int i = 0; i < 4; ++i)
                ((float4*)(sm + OFF_Y))[tid + i * NT] = __ldcg(ys + tid + i * NT);
            if (tid < WW)
                sm[OFF_RY + tid] = __ldcg(&g_rs[(((l - 1) * DD + slot) * PP + part) * WW + tid]);
            __syncthreads();
        } else {
            // own RY reduction over x columns (conflict-free two-pass)
            int col = tid & 63, sub = tid >> 6;
            float s1 = 0.f;
            #pragma unroll
            for (int i = 0; i < 16; ++i) {
                float a = sm[OFF_Y + (sub * 16 + i) * WW + col];
                s1 += a * a;
            }
            sm[OFF_SCR + sub * WW + col] = s1;
            __syncthreads();
            if (tid < WW) {
                float s = sm[OFF_SCR + tid] + sm[OFF_SCR + 64 + tid] + sm[OFF_SCR + 128 + tid]
                        + sm[OFF_SCR + 192 + tid] + sm[OFF_SCR + 256 + tid] + sm[OFF_SCR + 320 + tid];
                sm[OFF_RY + tid] = rsqrtf(s * (1.f / 96.f) + EPSF);
            }
            __syncthreads();
        }

        // ---- Phase C: fused dual GEMM; both weight paths pre-duplicated,
        //      double-buffered cp.async panels, LDS.64 straight into fma2 ----
        u64 AX0[8], AX1[8], AX2[8], AH0[8], AH1[8], AH2[8];
        #pragma unroll
        for (int j = 0; j < 8; ++j) {
            AX0[j]=0ULL; AX1[j]=0ULL; AX2[j]=0ULL;
            AH0[j]=0ULL; AH1[j]=0ULL; AH2[j]=0ULL;
        }
        #pragma unroll 1
        for (int p = 0; p < NPAN; ++p) {
            CP_WAIT0();
            __syncthreads();            // panel p visible; other buffer free
            if (p < NPAN - 1) {         // stage panel p+1 into other buffer
                unsigned dbase = wpbase + (unsigned)(((p + 1) & 1) * 2 * PANU) * 8u;
                #pragma unroll
                for (int i = 0; i < 6; ++i) {
                    const float4* src = (s_path[i] ? gh : gx) +
                        ((s_row[i] / PK) * CCH + (p + 1) * PK + (s_row[i] & (PK - 1))) * 48 + s_c4[i];
                    unsigned dst = dbase +
                        (unsigned)(s_path[i] * PANU + s_row[i] * CCH + s_c4[i] * 2) * 8u;
                    cp16(dst, src);
                }
                CP_COMMIT();
            }
            const u64* smw = (const u64*)(sm + OFF_WP) + (p & 1) * 2 * PANU;
            #pragma unroll
            for (int kk = 0; kk < PK; ++kk) {
                int k = p * PK + kk;
                u64 X0 = smw[          kk * CCH + c];
                u64 X1 = smw[ 768 +    kk * CCH + c];
                u64 X2 = smw[1536 +    kk * CCH + c];
                u64 H0 = smw[PANU +        kk * CCH + c];
                u64 H1 = smw[PANU + 768 +  kk * CCH + c];
                u64 H2 = smw[PANU + 1536 + kk * CCH + c];
                const ulonglong2* yp = (const ulonglong2*)(sm + OFF_Y  + k * WW + mb);
                const ulonglong2* hq = (const ulonglong2*)(sm + OFF_HC + k * WW + mb);
                ulonglong2 ya = yp[0], yb = yp[1], yc2 = yp[2], yd = yp[3];
                ulonglong2 ha = hq[0], hb2 = hq[1], hc2 = hq[2], hd = hq[3];
                u64 yv[8] = { ya.x, ya.y, yb.x, yb.y, yc2.x, yc2.y, yd.x, yd.y };
                u64 hv[8] = { ha.x, ha.y, hb2.x, hb2.y, hc2.x, hc2.y, hd.x, hd.y };
                #pragma unroll
                for (int j = 0; j < 8; ++j) {
                    AX0[j] = fma2(X0, yv[j], AX0[j]);
                    AX1[j] = fma2(X1, yv[j], AX1[j]);
                    AX2[j] = fma2(X2, yv[j], AX2[j]);
                    AH0[j] = fma2(H0, hv[j], AH0[j]);
                    AH1[j] = fma2(H1, hv[j], AH1[j]);
                    AH2[j] = fma2(H2, hv[j], AH2[j]);
                }
            }
        }

        // ---- Phase D: gates (RY post-GEMM), s = h_new + y ----
        float sv[16];
        #pragma unroll
        for (int j = 0; j < 8; ++j) {
            float2 x0 = unpack2(AX0[j]), x1 = unpack2(AX1[j]), x2 = unpack2(AX2[j]);
            float2 h0 = unpack2(AH0[j]), h1 = unpack2(AH1[j]), h2 = unpack2(AH2[j]);
            #pragma unroll
            for (int s2 = 0; s2 < 2; ++s2) {
                int m = mb + 2 * j + s2;
                float ry = sm[OFF_RY + m];
                float xr = ry * (s2 ? x0.y : x0.x) + xb0;
                float xz = ry * (s2 ? x1.y : x1.x) + xb1;
                float xn = ry * (s2 ? x2.y : x2.x) + xb2;
                float hr = (s2 ? h0.y : h0.x) + pb0;
                float hz = (s2 ? h1.y : h1.x) + pb1;
                float hn = (s2 ? h2.y : h2.x) + pb2;
                float r = fsigm(xr + hr);
                float z = fsigm(xz + hz);
                float cand = ftanh(xn + r * hn);
                float hpv = sm[OFF_HP + c * WW + m];
                float yv  = sm[OFF_Y  + c * WW + m];
                sv[2 * j + s2] = (1.f - z) * cand + z * hpv + yv;
            }
        }
        __syncthreads();   // all GEMM reads of HC/Y complete; reuse HC as s-buffer
        {
            float4* sp = (float4*)(sm + OFF_HC + c * WW + mb);
            sp[0] = make_float4(sv[0],  sv[1],  sv[2],  sv[3]);
            sp[1] = make_float4(sv[4],  sv[5],  sv[6],  sv[7]);
            sp[2] = make_float4(sv[8],  sv[9],  sv[10], sv[11]);
            sp[3] = make_float4(sv[12], sv[13], sv[14], sv[15]);
        }
        __syncthreads();

        // ---- out RMS + next RH, conflict-free two-pass dual accumulation ----
        {
            int col = tid & 63, sub = tid >> 6;
            float s1 = 0.f, s2a = 0.f;
            #pragma unroll
            for (int i = 0; i < 16; ++i) {
                int c2 = sub * 16 + i;
                float a  = sm[OFF_HC + c2 * WW + col];
                float aw = a * sm[OFF_ONW + c2];
                s1  += a * a;
                s2a += aw * aw;
            }
            sm[OFF_SCR + sub * WW + col]       = s1;
            sm[OFF_SCR + 384 + sub * WW + col] = s2a;
        }
        __syncthreads();
        if (tid < WW) {
            float s1 = 0.f, s2a = 0.f;
            #pragma unroll
            for (int sub = 0; sub < 6; ++sub) {
                s1  += sm[OFF_SCR + sub * WW + tid];
                s2a += sm[OFF_SCR + 384 + sub * WW + tid];
            }
            float ro = rsqrtf(s1 * (1.f / 96.f) + EPSF);
            sm[OFF_RO + tid] = ro;
            float rp = rsqrtf(ro * ro * s2a * (1.f / 96.f) + EPSF);
            sm[OFF_RH + tid] = rp;
            if (l < LL - 1)
                g_rs[((l * DD + slot) * PP + part) * WW + tid] = rp;
        }
        __syncthreads();

        // ---- Phase E: v = s*RO*onw -> HP + ring / out ----
        {
            float4* ring = (float4*)(g_hbuf + ((size_t)(l * DD + slot) * PP + part) * TILE);
            #pragma unroll
            for (int i = 0; i < 4; ++i) {
                int f4 = tid + i * NT;
                int cc = f4 >> 4, j = f4 & 15;
                float4 s4  = ((float4*)(sm + OFF_HC))[f4];
                float4 ro4 = ((float4*)(sm + OFF_RO))[j];
                float ow   = sm[OFF_ONW + cc];
                float4 v;
                v.x = s4.x * ro4.x * ow;
                v.y = s4.y * ro4.y * ow;
                v.z = s4.z * ro4.z * ow;
                v.w = s4.w * ro4.w * ow;
                ((float4*)(sm + OFF_HP))[f4] = v;
                if (l < LL - 1) ring[f4] = v;
                else ((float4*)(out + (((size_t)part * CCH + cc) * TT + t) * FF))[j] = v;
            }
        }
        __syncthreads();
        if (tid == 0) {
            __threadfence();                    // release (single fence per step)
            st_vol(myflag, t + 1);
        }
    }
}

// ---------------------------------------------------------------------------
extern "C" void kernel_launch(void* const* d_in, const int* in_sizes, int n_in,
                              void* d_out, int out_size) {
    const float* x    = (const float*)d_in[0];
    const float* inw  = (const float*)d_in[1];
    const float* hnw  = (const float*)d_in[2];
    const float* xpw  = (const float*)d_in[3];
    const float* xpb  = (const float*)d_in[4];
    const float* hmw  = (const float*)d_in[5];
    const float* hmb  = (const float*)d_in[6];
    const float* hpw  = (const float*)d_in[7];
    const float* hpb  = (const float*)d_in[8];
    const float* onw  = (const float*)d_in[9];
    float* out = (float*)d_out;

    cudaFuncSetAttribute(gru_main, cudaFuncAttributeMaxDynamicSharedMemorySize, SMEM_BYTES);

    gru_init<<<256, 256>>>(xpw, hpw, inw, hnw, hmb, hpb);
    gru_main<<<LL * PP, NT, SMEM_BYTES>>>(x, xpb, hmw, onw, out);
}

// round 17
// speedup vs baseline: 1.2409x; 1.2409x over previous
#include <cuda_runtime.h>

// Problem constants
#define CCH   96
#define TT    1000
#define FF    64
#define LL    12
#define PP    8           // parts = batch elements (zero conv halo)
#define NT    384         // 96 c-lanes x 4 col-groups (16 cols/thread)
#define DD    8           // state ring depth
#define WW    64
#define EPSF  1e-6f
#define TILE  (CCH * WW)  // 6144
#define NPAN  12          // weight panels per GEMM
#define PK    8           // k per panel

// ---------------- device globals (no runtime alloc) ------------------------
__device__ float  g_hbuf[LL * DD * PP * TILE];   // output ring (18.9 MB)
__device__ float  g_rs  [LL * DD * PP * WW];     // published rms stats
__device__ float  g_xw3 [LL * 3 * CCH * CCH];    // x-path folded weights [l][d][k][c]
__device__ float  g_pw3 [LL * 3 * CCH * CCH];    // h-path folded weights [l][d][k][c]
__device__ float  g_pbF [LL * 288];              // pb + pw . hb
__device__ int    g_prog[LL * PP * 32];          // flags, 128B padded

// smem layout (floats) — identical to R15
#define OFF_WH   0         // h-weights [d][k][c]   27648
#define OFF_Y    27648     // raw y                 6144
#define OFF_HP   33792     // prev output           6144
#define OFF_HC   39936     // conv / s-buffer       6144
#define OFF_RY   46080     // 64
#define OFF_RH   46144     // 64
#define OFF_RO   46208     // 64
#define OFF_SCR  46272     // reduction scratch     768
#define OFF_ONW  47040     // 96
#define OFF_XB   47136     // 288
#define OFF_PB   47424     // 288
#define OFF_HWT  47712     // conv taps [d][c] 3*96
#define OFF_XW   48000     // x-weight staging: 2 bufs x (3*8*96) = 4608
#define SMEM_FLOATS 52608
#define SMEM_BYTES  (SMEM_FLOATS * 4)   // 210,432 B

typedef unsigned long long u64;

__device__ __forceinline__ u64 fma2(u64 a, u64 b, u64 c) {
    u64 d;
    asm("fma.rn.f32x2 %0, %1, %2, %3;" : "=l"(d) : "l"(a), "l"(b), "l"(c));
    return d;
}
__device__ __forceinline__ u64 pack2(float x) {
    u64 d; asm("mov.b64 %0, {%1, %1};" : "=l"(d) : "f"(x)); return d;
}
__device__ __forceinline__ float2 unpack2(u64 v) {
    float2 r; asm("mov.b64 {%0, %1}, %2;" : "=f"(r.x), "=f"(r.y) : "l"(v)); return r;
}
__device__ __forceinline__ int ld_vol(const int* p) {
    int v;
    asm volatile("ld.volatile.global.b32 %0, [%1];" : "=r"(v) : "l"(p) : "memory");
    return v;
}
__device__ __forceinline__ void st_vol(int* p, int v) {
    asm volatile("st.volatile.global.b32 [%0], %1;" :: "l"(p), "r"(v) : "memory");
}
__device__ __forceinline__ void spin_ge(const int* p, int tgt) {
    while (ld_vol(p) < tgt) {
#if __CUDA_ARCH__ >= 700
        __nanosleep(40);
#endif
    }
}
__device__ __forceinline__ float fsigm(float x) {
    return __fdividef(1.f, 1.f + __expf(-x));
}
__device__ __forceinline__ float ftanh(float x) {
    float e = __expf(2.f * x);
    return 1.f - __fdividef(2.f, 1.f + e);
}
#define CP_COMMIT() asm volatile("cp.async.commit_group;")
#define CP_WAIT0()  asm volatile("cp.async.wait_group 0;")
__device__ __forceinline__ void cp16(unsigned dst, const float4* src) {
    asm volatile("cp.async.ca.shared.global [%0], [%1], 16;" :: "r"(dst), "l"(src));
}
__device__ __forceinline__ void cp16cg(unsigned dst, const float4* src) {
    asm volatile("cp.async.cg.shared.global [%0], [%1], 16;" :: "r"(dst), "l"(src));
}

// ---------------- init: flags + weight folding (R15 layout) ----------------
__global__ void gru_init(const float* __restrict__ xw, const float* __restrict__ pw,
                         const float* __restrict__ inw, const float* __restrict__ hnw,
                         const float* __restrict__ hb,  const float* __restrict__ pb) {
    int idx = blockIdx.x * blockDim.x + threadIdx.x;
    int stride = gridDim.x * blockDim.x;
    for (int i = idx; i < LL * PP * 32; i += stride) g_prog[i] = 0;
    const int NW = LL * CCH * CCH;
    for (int i = idx; i < NW; i += stride) {
        int l = i / (CCH * CCH), r = i - l * (CCH * CCH);
        int k = r / CCH, c = r - k * CCH;
        float fin = inw[l * CCH + k], fhn = hnw[l * CCH + k];
        #pragma unroll
        for (int d = 0; d < 3; ++d) {
            g_xw3[(((size_t)l * 3 + d) * CCH + k) * CCH + c] =
                xw[(l * 288 + d * CCH + c) * CCH + k] * fin;
            g_pw3[(((size_t)l * 3 + d) * CCH + k) * CCH + c] =
                pw[(l * 288 + d * CCH + c) * CCH + k] * fhn;
        }
    }
    for (int i = idx; i < LL * 288; i += stride) {
        int l = i / 288, o = i - l * 288;
        float s = pb[i];
        for (int k = 0; k < CCH; ++k) s += pw[(l * 288 + o) * CCH + k] * hb[l * CCH + k];
        g_pbF[i] = s;
    }
}

// ---------------- main persistent wavefront kernel -------------------------
__global__ void __launch_bounds__(NT, 1) gru_main(
    const float* __restrict__ x,
    const float* __restrict__ xpb_g,
    const float* __restrict__ hw_g,
    const float* __restrict__ onw_g,
    float* __restrict__ out)
{
    extern __shared__ float sm[];
    const int tid  = threadIdx.x;
    const int l    = blockIdx.x / PP;
    const int part = blockIdx.x % PP;      // = batch element

    // ---- one-time: params + h-path weights into smem ----
    for (int i = tid; i < CCH; i += NT) {
        sm[OFF_ONW + i]       = onw_g[l * CCH + i];
        sm[OFF_HWT       + i] = hw_g[(l * CCH + i) * 3 + 0];
        sm[OFF_HWT +  96 + i] = hw_g[(l * CCH + i) * 3 + 1];
        sm[OFF_HWT + 192 + i] = hw_g[(l * CCH + i) * 3 + 2];
    }
    for (int i = tid; i < 288; i += NT) {
        sm[OFF_XB + i] = xpb_g[l * 288 + i];
        sm[OFF_PB + i] = g_pbF[l * 288 + i];
    }
    {
        const float* pws = g_pw3 + (size_t)l * 3 * CCH * CCH;
        for (int i = tid; i < 3 * CCH * CCH; i += NT) sm[OFF_WH + i] = pws[i];
    }
    for (int i = tid; i < TILE; i += NT) sm[OFF_HP + i] = 0.f;
    if (tid < WW) sm[OFF_RH + tid] = 0.f;
    __syncthreads();

    const int c  = tid % CCH;
    const int mb = (tid / CCH) * 16;       // 16 cols per thread
    const float xb0 = sm[OFF_XB + c], xb1 = sm[OFF_XB + 96 + c], xb2 = sm[OFF_XB + 192 + c];
    const float pb0 = sm[OFF_PB + c], pb1 = sm[OFF_PB + 96 + c], pb2 = sm[OFF_PB + 192 + c];

    // x-weight panel staging setup (R15 scheme)
    unsigned xwbase, ybase;
    {
        const float* p0 = sm + OFF_XW;
        asm("{ .reg .u64 t; cvta.to.shared.u64 t, %1; cvt.u32.u64 %0, t; }"
            : "=r"(xwbase) : "l"(p0));
        const float* p1 = sm + OFF_Y;
        asm("{ .reg .u64 t; cvta.to.shared.u64 t, %1; cvt.u32.u64 %0, t; }"
            : "=r"(ybase) : "l"(p1));
    }
    const float4* __restrict__ gx = (const float4*)g_xw3 + (size_t)l * 3 * 2304;
    const int sd0 = tid / 192, sr0 = tid - sd0 * 192;

    int* myflag = &g_prog[(l * PP + part) * 32];

    #pragma unroll 1
    for (int t = 0; t < TT; ++t) {
        const int slot = t & (DD - 1);

        // ================= PRE-SPIN (own-state work only) =================
        // stage x-weight panel 0 into buf0 (prev step drained both buffers)
        cp16(xwbase + (unsigned)(sd0 * 192 + sr0) * 16, gx + sd0 * 2304 + sr0);
        if (tid < 192)
            cp16(xwbase + (unsigned)(2 * 192 + tid) * 16, gx + 2 * 2304 + tid);
        CP_COMMIT();

        if (l == 0) {      // x is a pure input: load now
            #pragma unroll
            for (int i = 0; i < 4; ++i) {
                int f4 = tid + i * NT;
                int cc = f4 >> 4, j = f4 & 15;
                ((float4*)(sm + OFF_Y))[f4] =
                    __ldg((const float4*)(x + (((size_t)part * CCH + cc) * TT + t) * FF) + j);
            }
        }
        // conv: hc = dwconv(hp * RH)
        #pragma unroll
        for (int i = 0; i < 16; ++i) {
            int idx = tid + i * NT;
            int cc = idx >> 6, m = idx & 63;
            float acc = sm[OFF_HP + idx] * sm[OFF_RH + m] * sm[OFF_HWT + 96 + cc];
            if (m != 0)  acc += sm[OFF_HP + idx - 1] * sm[OFF_RH + m - 1] * sm[OFF_HWT + cc];
            if (m != 63) acc += sm[OFF_HP + idx + 1] * sm[OFF_RH + m + 1] * sm[OFF_HWT + 192 + cc];
            sm[OFF_HC + idx] = acc;
        }
        __syncthreads();   // HC (and Y for l==0) visible

        if (l == 0) {      // own RY reduction (pre-spin; conflict-free two-pass)
            int col = tid & 63, sub = tid >> 6;
            float s1 = 0.f;
            #pragma unroll
            for (int i = 0; i < 16; ++i) {
                float a = sm[OFF_Y + (sub * 16 + i) * WW + col];
                s1 += a * a;
            }
            sm[OFF_SCR + sub * WW + col] = s1;
            __syncthreads();
            if (tid < WW) {
                float s = sm[OFF_SCR + tid] + sm[OFF_SCR + 64 + tid] + sm[OFF_SCR + 128 + tid]
                        + sm[OFF_SCR + 192 + tid] + sm[OFF_SCR + 256 + tid] + sm[OFF_SCR + 320 + tid];
                sm[OFF_RY + tid] = rsqrtf(s * (1.f / 96.f) + EPSF);
            }
            __syncthreads();
        }

        // h-path GEMM (persistent smem weights) — runs before any neighbor dep
        u64 AH0[8], AH1[8], AH2[8];
        #pragma unroll
        for (int j = 0; j < 8; ++j) { AH0[j]=0ULL; AH1[j]=0ULL; AH2[j]=0ULL; }
        #pragma unroll 4
        for (int k = 0; k < CCH; ++k) {
            u64 H0 = pack2(sm[OFF_WH +          k * CCH + c]);
            u64 H1 = pack2(sm[OFF_WH +  9216 +  k * CCH + c]);
            u64 H2 = pack2(sm[OFF_WH + 18432 +  k * CCH + c]);
            const u64* hq = (const u64*)(sm + OFF_HC + k * WW + mb);
            #pragma unroll
            for (int j = 0; j < 8; ++j) {
                u64 hv = hq[j];
                AH0[j] = fma2(H0, hv, AH0[j]);
                AH1[j] = fma2(H1, hv, AH1[j]);
                AH2[j] = fma2(H2, hv, AH2[j]);
            }
        }

        // ================= SPIN =================
        if (tid == 0) {
            if (l > 0)                 spin_ge(&g_prog[((l - 1) * PP + part) * 32], t + 1);
            if (l < LL - 1 && t >= DD) spin_ge(&g_prog[((l + 1) * PP + part) * 32], t - DD + 1);
        }
        __syncthreads();

        // ---- Phase A: y via cp.async.cg (L2-direct), RY via __ldcg ----
        if (l > 0) {
            const float4* ys = (const float4*)(g_hbuf +
                ((size_t)((l - 1) * DD + slot) * PP + part) * TILE);
            #pragma unroll
            for (int i = 0; i < 4; ++i)
                cp16cg(ybase + (unsigned)(tid + i * NT) * 16, ys + tid + i * NT);
            CP_COMMIT();
            if (tid < WW)
                sm[OFF_RY + tid] = __ldcg(&g_rs[(((l - 1) * DD + slot) * PP + part) * WW + tid]);
        }

        // ---- x-path GEMM: cp.async panel pipeline (drains Y group too) ----
        u64 AX0[8], AX1[8], AX2[8];
        #pragma unroll
        for (int j = 0; j < 8; ++j) { AX0[j]=0ULL; AX1[j]=0ULL; AX2[j]=0ULL; }
        #pragma unroll 1
        for (int p = 0; p < NPAN; ++p) {
            CP_WAIT0();
            __syncthreads();            // panel p (and Y, p==0) visible
            if (p < NPAN - 1) {         // stage panel p+1 into other buffer
                unsigned dbase = xwbase + (unsigned)(((p + 1) & 1) * 2304) * 4;
                cp16(dbase + (unsigned)(sd0 * 192 + sr0) * 16,
                     gx + sd0 * 2304 + (p + 1) * 192 + sr0);
                if (tid < 192)
                    cp16(dbase + (unsigned)(2 * 192 + tid) * 16,
                         gx + 2 * 2304 + (p + 1) * 192 + tid);
                CP_COMMIT();
            }
            const float* smx = sm + OFF_XW + (p & 1) * 2304;
            #pragma unroll
            for (int kk = 0; kk < PK; ++kk) {
                int k = p * PK + kk;
                u64 X0 = pack2(smx[           kk * CCH + c]);
                u64 X1 = pack2(smx[ 768 +     kk * CCH + c]);
                u64 X2 = pack2(smx[1536 +     kk * CCH + c]);
                const u64* yp = (const u64*)(sm + OFF_Y + k * WW + mb);
                #pragma unroll
                for (int j = 0; j < 8; ++j) {
                    u64 yv = yp[j];
                    AX0[j] = fma2(X0, yv, AX0[j]);
                    AX1[j] = fma2(X1, yv, AX1[j]);
                    AX2[j] = fma2(X2, yv, AX2[j]);
                }
            }
        }

        // ---- Phase D: gates (RY post-GEMM), s = h_new + y ----
        float sv[16];
        #pragma unroll
        for (int j = 0; j < 8; ++j) {
            float2 x0 = unpack2(AX0[j]), x1 = unpack2(AX1[j]), x2 = unpack2(AX2[j]);
            float2 h0 = unpack2(AH0[j]), h1 = unpack2(AH1[j]), h2 = unpack2(AH2[j]);
            #pragma unroll
            for (int s2 = 0; s2 < 2; ++s2) {
                int m = mb + 2 * j + s2;
                float ry = sm[OFF_RY + m];
                float xr = ry * (s2 ? x0.y : x0.x) + xb0;
                float xz = ry * (s2 ? x1.y : x1.x) + xb1;
                float xn = ry * (s2 ? x2.y : x2.x) + xb2;
                float hr = (s2 ? h0.y : h0.x) + pb0;
                float hz = (s2 ? h1.y : h1.x) + pb1;
                float hn = (s2 ? h2.y : h2.x) + pb2;
                float r = fsigm(xr + hr);
                float z = fsigm(xz + hz);
                float cand = ftanh(xn + r * hn);
                float hpv = sm[OFF_HP + c * WW + m];
                float yv  = sm[OFF_Y  + c * WW + m];
                sv[2 * j + s2] = (1.f - z) * cand + z * hpv + yv;
            }
        }
        __syncthreads();   // all GEMM reads of HC/Y complete; reuse HC as s-buffer
        {
            float4* sp = (float4*)(sm + OFF_HC + c * WW + mb);
            sp[0] = make_float4(sv[0],  sv[1],  sv[2],  sv[3]);
            sp[1] = make_float4(sv[4],  sv[5],  sv[6],  sv[7]);
            sp[2] = make_float4(sv[8],  sv[9],  sv[10], sv[11]);
            sp[3] = make_float4(sv[12], sv[13], sv[14], sv[15]);
        }
        __syncthreads();

        // ---- out RMS + next RH, conflict-free two-pass dual accumulation ----
        {
            int col = tid & 63, sub = tid >> 6;
            float s1 = 0.f, s2a = 0.f;
            #pragma unroll
            for (int i = 0; i < 16; ++i) {
                int c2 = sub * 16 + i;
                float a  = sm[OFF_HC + c2 * WW + col];
                float aw = a * sm[OFF_ONW + c2];
                s1  += a * a;
                s2a += aw * aw;
            }
            sm[OFF_SCR + sub * WW + col]       = s1;
            sm[OFF_SCR + 384 + sub * WW + col] = s2a;
        }
        __syncthreads();
        if (tid < WW) {
            float s1 = 0.f, s2a = 0.f;
            #pragma unroll
            for (int sub = 0; sub < 6; ++sub) {
                s1  += sm[OFF_SCR + sub * WW + tid];
                s2a += sm[OFF_SCR + 384 + sub * WW + tid];
            }
            float ro = rsqrtf(s1 * (1.f / 96.f) + EPSF);
            sm[OFF_RO + tid] = ro;
            float rp = rsqrtf(ro * ro * s2a * (1.f / 96.f) + EPSF);
            sm[OFF_RH + tid] = rp;
            if (l < LL - 1)
                g_rs[((l * DD + slot) * PP + part) * WW + tid] = rp;
        }
        __syncthreads();

        // ---- Phase E: v = s*RO*onw -> HP + ring / out ----
        {
            float4* ring = (float4*)(g_hbuf + ((size_t)(l * DD + slot) * PP + part) * TILE);
            #pragma unroll
            for (int i = 0; i < 4; ++i) {
                int f4 = tid + i * NT;
                int cc = f4 >> 4, j = f4 & 15;
                float4 s4  = ((float4*)(sm + OFF_HC))[f4];
                float4 ro4 = ((float4*)(sm + OFF_RO))[j];
                float ow   = sm[OFF_ONW + cc];
                float4 v;
                v.x = s4.x * ro4.x * ow;
                v.y = s4.y * ro4.y * ow;
                v.z = s4.z * ro4.z * ow;
                v.w = s4.w * ro4.w * ow;
                ((float4*)(sm + OFF_HP))[f4] = v;
                if (l < LL - 1) ring[f4] = v;
                else ((float4*)(out + (((size_t)part * CCH + cc) * TT + t) * FF))[j] = v;
            }
        }
        __syncthreads();
        if (tid == 0) {
            __threadfence();                    // release (single fence per step)
            st_vol(myflag, t + 1);
        }
    }
}

// ---------------------------------------------------------------------------
extern "C" void kernel_launch(void* const* d_in, const int* in_sizes, int n_in,
                              void* d_out, int out_size) {
    const float* x    = (const float*)d_in[0];
    const float* inw  = (const float*)d_in[1];
    const float* hnw  = (const float*)d_in[2];
    const float* xpw  = (const float*)d_in[3];
    const float* xpb  = (const float*)d_in[4];
    const float* hmw  = (const float*)d_in[5];
    const float* hmb  = (const float*)d_in[6];
    const float* hpw  = (const float*)d_in[7];
    const float* hpb  = (const float*)d_in[8];
    const float* onw  = (const float*)d_in[9];
    float* out = (float*)d_out;

    cudaFuncSetAttribute(gru_main, cudaFuncAttributeMaxDynamicSharedMemorySize, SMEM_BYTES);

    gru_init<<<256, 256>>>(xpw, hpw, inw, hnw, hmb, hpb);
    gru_main<<<LL * PP, NT, SMEM_BYTES>>>(x, xpb, hmw, onw, out);
}